// round 11
// baseline (speedup 1.0000x reference)
#include <cuda_runtime.h>

#define DIM 64
#define KNB 16
#define NREL 33
#define W0PAD 17   // float4 per row -> conflict-free LDS.128

__global__ __launch_bounds__(256, 5) void kgnn_kernel(
    const int* __restrict__ u_ids,
    const int* __restrict__ i_ids,
    const int* __restrict__ adj_entity,
    const int* __restrict__ adj_relation,
    const float* __restrict__ user_emb,
    const float* __restrict__ entity_emb,
    const float* __restrict__ relation_emb,
    const float* __restrict__ W0,
    const float* __restrict__ b0,
    const float* __restrict__ W1,
    const float* __restrict__ b1,
    float* __restrict__ out,
    int B)
{
    // flat groups: g = elem*16 + j (hop-1), g = 32+elem (hop-0)
    // warp w owns groups 4w..4w+3; warps 6,7 additionally own 32,33
    __shared__ float4 W0_s[64 * W0PAD];
    __shared__ float  ue_s[2][64];
    __shared__ float  ex_s[2][NREL];
    __shared__ float  attn0_s[2][16];
    __shared__ int    e1_s[2][16], r0_s[2][16];
    __shared__ __align__(16) float x_s[34][64];   // x, then (in-place) h
    __shared__ __align__(16) float xf_s[2][64];
    __shared__ float  red_s[2][2];

    const int b    = blockIdx.x;
    const int t    = threadIdx.x;
    const int lane = t & 31;
    const int w    = t >> 5;
    const int bi0  = 2 * b;
    const int bi1  = (2 * b + 1 < B) ? (2 * b + 1) : (B - 1);

    // ---- P1: stage W0, ue x2, hop-0 indices x2 ----
    {
        const float4* W0_4 = (const float4*)W0;
        #pragma unroll
        for (int i = 0; i < 4; i++) {
            int idx = t + i * 256;
            int e = idx >> 4, c = idx & 15;
            W0_s[e * W0PAD + c] = W0_4[idx];
        }
    }
    if (t < 128) {
        const int elem = t >> 6, d = t & 63;
        const int bi = elem ? bi1 : bi0;
        ue_s[elem][d] = user_emb[u_ids[bi] * 64 + d];
    }
    if (t < 32) {
        const int elem = t >> 4, kk = t & 15;
        const int bi = elem ? bi1 : bi0;
        const int e0 = i_ids[bi];
        e1_s[elem][kk] = adj_entity[e0 * KNB + kk];
        r0_s[elem][kk] = adj_relation[e0 * KNB + kk];
    }
    __syncthreads();

    // ---- P2: 66 relation exp-dots (all warps) ----
    for (int idx = w; idx < 2 * NREL; idx += 8) {
        const int r = idx >> 1, elem = idx & 1;
        float p = ue_s[elem][lane] * relation_emb[r * 64 + lane]
                + ue_s[elem][lane + 32] * relation_emb[r * 64 + 32 + lane];
        #pragma unroll
        for (int o = 16; o; o >>= 1) p += __shfl_xor_sync(0xffffffffu, p, o);
        if (lane == 0) ex_s[elem][r] = __expf(p * (1.f / 64.f));
    }
    __syncthreads();

    // ---- Phase A (warp-local): attention + gather for owned groups ----
    const int half = lane >> 4;
    const int c    = lane & 15;
    const int kl   = lane & 15;

    #pragma unroll
    for (int p = 0; p < 2; p++) {
        const int gp = 4 * w + 2 * p;              // pair: gp, gp+1
        const int gmine = gp + half;
        const int elem  = gmine >> 4, j = gmine & 15;
        const int ej = e1_s[elem][j];
        const int eid = adj_entity[ej * KNB + kl];
        const int rid = adj_relation[ej * KNB + kl];
        float ex = ex_s[elem][rid];
        float sum = ex;
        #pragma unroll
        for (int o = 8; o; o >>= 1) sum += __shfl_xor_sync(0xffffffffu, sum, o);
        const float at = __fdividef(ex, sum * 16.f);

        #pragma unroll
        for (int pos = 0; pos < 2; pos++) {
            const int g = gp + pos;
            float4 acc = make_float4(0.f, 0.f, 0.f, 0.f);
            #pragma unroll
            for (int kk = 0; kk < 8; kk++) {
                const int k = kk * 2 + half;
                const int src = pos * 16 + k;
                const int id = __shfl_sync(0xffffffffu, eid, src);
                const float a = __shfl_sync(0xffffffffu, at, src);
                const float4 v = ((const float4*)(entity_emb + id * 64))[c];
                acc.x += a * v.x; acc.y += a * v.y; acc.z += a * v.z; acc.w += a * v.w;
            }
            acc.x += __shfl_xor_sync(0xffffffffu, acc.x, 16);
            acc.y += __shfl_xor_sync(0xffffffffu, acc.y, 16);
            acc.z += __shfl_xor_sync(0xffffffffu, acc.z, 16);
            acc.w += __shfl_xor_sync(0xffffffffu, acc.w, 16);
            if (half == 0) {
                const float4 sv = ((const float4*)(entity_emb + e1_s[g >> 4][g & 15] * 64))[c];
                ((float4*)x_s[g])[c] = make_float4(sv.x + acc.x, sv.y + acc.y,
                                                   sv.z + acc.z, sv.w + acc.w);
            }
        }
    }
    if (w >= 6) {   // hop-0 group g5 = 32+elem
        const int elem = w - 6;
        const int g5 = 32 + elem;
        const int eid5 = e1_s[elem][kl];
        const int rid5 = r0_s[elem][kl];
        float ex = ex_s[elem][rid5];
        float sum = ex;
        #pragma unroll
        for (int o = 8; o; o >>= 1) sum += __shfl_xor_sync(0xffffffffu, sum, o);
        const float at5 = __fdividef(ex, sum * 16.f);
        if (lane < 16) attn0_s[elem][kl] = at5;    // needed by P6

        float4 acc = make_float4(0.f, 0.f, 0.f, 0.f);
        #pragma unroll
        for (int kk = 0; kk < 8; kk++) {
            const int k = kk * 2 + half;
            const int id = __shfl_sync(0xffffffffu, eid5, k);
            const float a = __shfl_sync(0xffffffffu, at5, k);
            const float4 v = ((const float4*)(entity_emb + id * 64))[c];
            acc.x += a * v.x; acc.y += a * v.y; acc.z += a * v.z; acc.w += a * v.w;
        }
        acc.x += __shfl_xor_sync(0xffffffffu, acc.x, 16);
        acc.y += __shfl_xor_sync(0xffffffffu, acc.y, 16);
        acc.z += __shfl_xor_sync(0xffffffffu, acc.z, 16);
        acc.w += __shfl_xor_sync(0xffffffffu, acc.w, 16);
        if (half == 0) {
            const int bi = elem ? bi1 : bi0;
            const float4 sv = ((const float4*)(entity_emb + i_ids[bi] * 64))[c];
            ((float4*)x_s[g5])[c] = make_float4(sv.x + acc.x, sv.y + acc.y,
                                                sv.z + acc.z, sv.w + acc.w);
        }
    }
    __syncwarp();   // order warp-local x_s writes before warp-local reads

    // ---- P5 (warp-local): matvecs for owned slots, ONE W pass, in-place h ----
    {
        const float* xflat = &x_s[0][0];
        const float bl = b0[lane], bh = b0[lane + 32];
        float al[4], ah[4];
        #pragma unroll
        for (int q = 0; q < 4; q++) { al[q] = bl; ah[q] = bh; }
        float al5 = bl, ah5 = bh;
        const int f4 = w * 4;
        const int f5 = 26 + w;                 // valid for w>=6
        const bool has5 = (w >= 6);
        #pragma unroll
        for (int dd = 0; dd < 16; dd++) {
            const float4 wl = W0_s[lane * W0PAD + dd];
            const float4 wh = W0_s[(lane + 32) * W0PAD + dd];
            #pragma unroll
            for (int q = 0; q < 4; q++) {
                const float4 xv = ((const float4*)(xflat + (f4 + q) * 64))[dd];
                al[q] += xv.x*wl.x + xv.y*wl.y + xv.z*wl.z + xv.w*wl.w;
                ah[q] += xv.x*wh.x + xv.y*wh.y + xv.z*wh.z + xv.w*wh.w;
            }
            if (has5) {
                const float4 xv = ((const float4*)(xflat + f5 * 64))[dd];
                al5 += xv.x*wl.x + xv.y*wl.y + xv.z*wl.z + xv.w*wl.w;
                ah5 += xv.x*wh.x + xv.y*wh.y + xv.z*wh.z + xv.w*wh.w;
            }
        }
        #pragma unroll
        for (int q = 0; q < 4; q++) {
            x_s[f4 + q][lane]      = fmaxf(al[q], 0.f);
            x_s[f4 + q][lane + 32] = fmaxf(ah[q], 0.f);
        }
        if (has5) {
            x_s[f5][lane]      = fmaxf(al5, 0.f);
            x_s[f5][lane + 32] = fmaxf(ah5, 0.f);
        }
    }
    __syncthreads();

    // ---- P6: layer-1 hop-0 combine, tanh matvec, score ----
    if (t < 128) {
        const int elem = t >> 6, d = t & 63;
        float agg = 0.f;
        #pragma unroll
        for (int k = 0; k < 16; k++) agg += attn0_s[elem][k] * x_s[elem * 16 + k][d];
        xf_s[elem][d] = x_s[32 + elem][d] + agg;
    }
    __syncthreads();
    if (t < 128) {
        const int elem = t >> 6, d = t & 63;
        float acc = b1[d];
        const float4* w1r = (const float4*)(W1 + d * 64);
        const float4* x0v = (const float4*)xf_s[elem];
        #pragma unroll
        for (int dd = 0; dd < 16; dd++) {
            const float4 xv = x0v[dd];
            const float4 wv = w1r[dd];
            acc += xv.x * wv.x + xv.y * wv.y + xv.z * wv.z + xv.w * wv.w;
        }
        const float item = tanhf(acc);
        float p = ue_s[elem][d] * item;
        #pragma unroll
        for (int o = 16; o; o >>= 1) p += __shfl_xor_sync(0xffffffffu, p, o);
        if (lane == 0) red_s[elem][w & 1] = p;
    }
    __syncthreads();
    if (t < 2) {
        const int bi = 2 * b + t;
        if (bi < B) {
            const float s = red_s[t][0] + red_s[t][1];
            out[bi] = 1.f / (1.f + __expf(-s));
        }
    }
}

extern "C" void kernel_launch(void* const* d_in, const int* in_sizes, int n_in,
                              void* d_out, int out_size) {
    const int*   u_ids        = (const int*)d_in[0];
    const int*   i_ids        = (const int*)d_in[1];
    const int*   adj_entity   = (const int*)d_in[2];
    const int*   adj_relation = (const int*)d_in[3];
    const float* user_emb     = (const float*)d_in[4];
    const float* entity_emb   = (const float*)d_in[5];
    const float* relation_emb = (const float*)d_in[6];
    const float* W0           = (const float*)d_in[7];
    const float* b0           = (const float*)d_in[8];
    const float* W1           = (const float*)d_in[9];
    const float* b1           = (const float*)d_in[10];
    float* out = (float*)d_out;

    const int B = in_sizes[1];
    const int grid = (B + 1) / 2;
    kgnn_kernel<<<grid, 256>>>(u_ids, i_ids, adj_entity, adj_relation,
                               user_emb, entity_emb, relation_emb,
                               W0, b0, W1, b1, out, B);
}